// round 16
// baseline (speedup 1.0000x reference)
#include <cuda_runtime.h>
#include <cuda.h>
#include <cuda_bf16.h>
#include <cstdint>

// 8x8 DCT-II coefficients, 0.5*cos(pi*(2m+1)k/16) pre-folded (orthonormal).
#define K0 0.3535533905932738f   // 1/(2*sqrt(2))
#define K1 0.4903926402016152f
#define K2 0.4619397662556434f
#define K3 0.4157348061512726f
#define K5 0.2777851165098011f
#define K6 0.1913417161825449f
#define K7 0.0975451610080642f

// SW128 swizzle (Swizzle<3,4,3>): XOR bits[6:4] with bits[9:7].
#define SWZ(o) ((o) ^ (((o) >> 3) & 0x70))

// In-place 8-point DCT-II (orthonormal), butterfly (even/odd) form.
__device__ __forceinline__ void dct8(float* v) {
    float s0 = v[0] + v[7], s1 = v[1] + v[6], s2 = v[2] + v[5], s3 = v[3] + v[4];
    float d0 = v[0] - v[7], d1 = v[1] - v[6], d2 = v[2] - v[5], d3 = v[3] - v[4];
    float e0 = s0 + s3, e1 = s1 + s2;
    float o0 = s0 - s3, o1 = s1 - s2;
    v[0] = K0 * (e0 + e1);
    v[4] = K0 * (e0 - e1);
    v[2] = K2 * o0 + K6 * o1;
    v[6] = K6 * o0 - K2 * o1;
    v[1] = K1 * d0 + K3 * d1 + K5 * d2 + K7 * d3;
    v[3] = K3 * d0 - K7 * d1 - K1 * d2 - K5 * d3;
    v[5] = K5 * d0 - K1 * d1 + K7 * d2 + K3 * d3;
    v[7] = K7 * d0 - K5 * d1 + K3 * d2 - K1 * d3;
}

// Waits on mbarrier at smem addr mb for given phase parity.
__device__ __forceinline__ void mbar_wait(uint32_t mb, uint32_t ph) {
    uint32_t done;
    asm volatile(
        "{\n\t.reg .pred p;\n\t"
        "mbarrier.try_wait.parity.acquire.cta.shared::cta.b64 p, [%1], %2;\n\t"
        "selp.b32 %0, 1, 0, p;\n\t}"
        : "=r"(done) : "r"(mb), "r"(ph) : "memory");
    if (!done) {
        asm volatile(
            "{\n\t.reg .pred P1;\n\t"
            "WL_%=:\n\t"
            "mbarrier.try_wait.parity.acquire.cta.shared::cta.b64 P1, [%0], %1, 0x989680;\n\t"
            "@P1 bra.uni WD_%=;\n\t"
            "bra.uni WL_%=;\n\t"
            "WD_%=:\n\t}"
            :: "r"(mb), "r"(ph) : "memory");
    }
}

#define ITERS 4

// CTA pipeline: 4 boxes (64 rows x 32 cols, 8KB each), 2-stage double buffer.
// Prefetch 2 boxes; per iter: wait full[s] -> 8 warps compute (swizzled LDS ->
// row DCT -> padded transpose -> col DCT -> quant -> swizzled STS to out[s])
// -> syncthreads -> tid0: TMA store out[s] (bulk group) + prefetch box i+2
// into in[s] -> wait_group 1 (bounds out-buffer reuse). Zero LDG/STG.
__global__ void __launch_bounds__(256)
dct_quant_pipe_kernel(const __grid_constant__ CUtensorMap tmi,
                      const __grid_constant__ CUtensorMap tmo,
                      const float* __restrict__ q) {
    __shared__ alignas(1024) float bin[2][2048];    // 2 x 8KB in-stages
    __shared__ alignas(1024) float bout[2][2048];   // 2 x 8KB out-stages
    __shared__ float tr[8][4][8][9];                // per-warp transpose, pad 9
    __shared__ float srq[64];
    __shared__ alignas(8) unsigned long long full[2];

    const int tid  = threadIdx.x;
    const int wid  = tid >> 5;
    const int lane = tid & 31;
    const int j    = lane >> 2;   // row within block -> horizontal freq index
    const int b    = lane & 3;    // block within warp tile

    const uint32_t mb0 = (uint32_t)__cvta_generic_to_shared(&full[0]);
    const uint32_t mb1 = (uint32_t)__cvta_generic_to_shared(&full[1]);
    const uint32_t si0 = (uint32_t)__cvta_generic_to_shared(&bin[0][0]);
    const uint32_t si1 = (uint32_t)__cvta_generic_to_shared(&bin[1][0]);

    if (tid < 64) srq[tid] = 1.0f / q[tid];
    if (tid == 0) {
        asm volatile("mbarrier.init.shared.b64 [%0], %1;" :: "r"(mb0), "r"(1u) : "memory");
        asm volatile("mbarrier.init.shared.b64 [%0], %1;" :: "r"(mb1), "r"(1u) : "memory");
    }
    __syncthreads();

    // Box id -> coords: 16384 boxes = 4096 row-bands (64 rows) x 4 col-groups.
    const int box0 = blockIdx.x * ITERS;

    if (tid == 0) {
        // Prefetch boxes 0 and 1.
        #pragma unroll
        for (int p = 0; p < 2; p++) {
            int id = box0 + p;
            int cx = (id & 3) << 5, cy = (id >> 2) << 6;
            uint32_t mb = p ? mb1 : mb0;
            uint32_t si = p ? si1 : si0;
            asm volatile("mbarrier.arrive.expect_tx.shared.b64 _, [%0], %1;"
                         :: "r"(mb), "r"(8192u) : "memory");
            asm volatile(
                "cp.async.bulk.tensor.2d.shared::cta.global.tile.mbarrier::complete_tx::bytes "
                "[%0], [%1, {%2, %3}], [%4];"
                :: "r"(si), "l"(&tmi), "r"(cx), "r"(cy), "r"(mb) : "memory");
        }
    }

    const uint32_t base0 = SWZ((uint32_t)((wid * 8 + j) * 128 + b * 32));
    const uint32_t base1 = SWZ((uint32_t)((wid * 8 + j) * 128 + b * 32 + 16));
    float* ts = &tr[wid][b][0][0];

    #pragma unroll
    for (int i = 0; i < ITERS; i++) {
        const int s  = i & 1;
        const uint32_t ph = (uint32_t)((i >> 1) & 1);
        const uint32_t mb = s ? mb1 : mb0;

        mbar_wait(mb, ph);

        // ---- compute this warp's 8x32 tile (rows wid*8..wid*8+7 of the box)
        float r[8];
        {
            const char* sb = reinterpret_cast<const char*>(&bin[s][0]);
            float4 lo = *reinterpret_cast<const float4*>(sb + base0);
            float4 hi = *reinterpret_cast<const float4*>(sb + base1);
            r[0] = lo.x; r[1] = lo.y; r[2] = lo.z; r[3] = lo.w;
            r[4] = hi.x; r[5] = hi.y; r[6] = hi.z; r[7] = hi.w;
        }

        dct8(r);                                   // row pass

        #pragma unroll
        for (int c = 0; c < 8; c++) ts[c * 9 + j] = r[c];
        __syncwarp();
        #pragma unroll
        for (int i2 = 0; i2 < 8; i2++) r[i2] = ts[j * 9 + i2];

        dct8(r);                                   // column pass

        {
            char* ob = reinterpret_cast<char*>(&bout[s][0]);
            #pragma unroll
            for (int v = 0; v < 8; v++) {
                float y = rintf(r[v] * srq[v * 8 + j]);
                y = fminf(fmaxf(y, -128.0f), 127.0f);
                uint32_t boff = (uint32_t)((wid * 8 + v) * 128 + (b * 8 + j) * 4);
                *reinterpret_cast<float*>(ob + SWZ(boff)) = y;
            }
        }

        __syncthreads();   // out[s] complete; all warps done reading in[s]

        if (tid == 0) {
            int id = box0 + i;
            int cx = (id & 3) << 5, cy = (id >> 2) << 6;
            uint32_t so = (uint32_t)__cvta_generic_to_shared(&bout[s][0]);
            asm volatile("fence.proxy.async.shared::cta;" ::: "memory");
            asm volatile(
                "cp.async.bulk.tensor.2d.global.shared::cta.tile.bulk_group "
                "[%0, {%1, %2}], [%3];"
                :: "l"(&tmo), "r"(cx), "r"(cy), "r"(so) : "memory");
            asm volatile("cp.async.bulk.commit_group;" ::: "memory");

            if (i + 2 < ITERS) {
                int id2 = box0 + i + 2;
                int cx2 = (id2 & 3) << 5, cy2 = (id2 >> 2) << 6;
                uint32_t si = s ? si1 : si0;
                asm volatile("mbarrier.arrive.expect_tx.shared.b64 _, [%0], %1;"
                             :: "r"(mb), "r"(8192u) : "memory");
                asm volatile(
                    "cp.async.bulk.tensor.2d.shared::cta.global.tile.mbarrier::complete_tx::bytes "
                    "[%0], [%1, {%2, %3}], [%4];"
                    :: "r"(si), "l"(&tmi), "r"(cx2), "r"(cy2), "r"(mb) : "memory");
            }

            if (i == ITERS - 1) {
                // Drain all stores before smem is released at CTA exit.
                asm volatile("cp.async.bulk.wait_group 0;" ::: "memory");
            } else {
                // Allow 1 outstanding store group; bounds out-buffer reuse.
                asm volatile("cp.async.bulk.wait_group 1;" ::: "memory");
            }
        }
        __syncthreads();
    }
}

// ---------------- host side ----------------

typedef CUresult (*PFN_encodeTiled)(
    CUtensorMap*, CUtensorMapDataType, cuuint32_t, void*,
    const cuuint64_t*, const cuuint64_t*, const cuuint32_t*, const cuuint32_t*,
    CUtensorMapInterleave, CUtensorMapSwizzle, CUtensorMapL2promotion,
    CUtensorMapFloatOOBfill);

static void encode_map(PFN_encodeTiled fn, CUtensorMap* tm, void* ptr) {
    cuuint64_t dims[2]    = {128, 262144};      // width (elems), height (rows)
    cuuint64_t strides[1] = {512};              // row stride in bytes
    cuuint32_t box[2]     = {32, 64};           // 128B x 64 rows = 8KB
    cuuint32_t estr[2]    = {1, 1};
    fn(tm, CU_TENSOR_MAP_DATA_TYPE_FLOAT32, 2, ptr,
       dims, strides, box, estr,
       CU_TENSOR_MAP_INTERLEAVE_NONE, CU_TENSOR_MAP_SWIZZLE_128B,
       CU_TENSOR_MAP_L2_PROMOTION_L2_128B, CU_TENSOR_MAP_FLOAT_OOB_FILL_NONE);
}

extern "C" void kernel_launch(void* const* d_in, const int* in_sizes, int n_in,
                              void* d_out, int out_size) {
    const float* x = (const float*)d_in[0];
    const float* q = (const float*)d_in[1];
    float* out = (float*)d_out;

    // Resolve cuTensorMapEncodeTiled through the runtime (no -lcuda needed).
    PFN_encodeTiled fn = nullptr;
    {
        void* p = nullptr;
        cudaDriverEntryPointQueryResult qr;
        cudaGetDriverEntryPointByVersion("cuTensorMapEncodeTiled", &p, 12050,
                                         cudaEnableDefault, &qr);
        fn = (PFN_encodeTiled)p;
    }

    CUtensorMap tmi, tmo;
    encode_map(fn, &tmi, (void*)x);
    encode_map(fn, &tmo, (void*)out);

    // 16384 boxes / 4 per CTA = 4096 CTAs
    dct_quant_pipe_kernel<<<4096, 256>>>(tmi, tmo, q);
}

// round 17
// speedup vs baseline: 1.0680x; 1.0680x over previous
#include <cuda_runtime.h>
#include <cuda_bf16.h>
#include <cstdint>

// 8x8 DCT-II coefficients, 0.5*cos(pi*(2m+1)k/16) pre-folded (orthonormal).
#define K0 0.3535533905932738f   // 1/(2*sqrt(2))
#define K1 0.4903926402016152f
#define K2 0.4619397662556434f
#define K3 0.4157348061512726f
#define K5 0.2777851165098011f
#define K6 0.1913417161825449f
#define K7 0.0975451610080642f

// In-place 8-point DCT-II (orthonormal), butterfly (even/odd) form.
__device__ __forceinline__ void dct8(float* v) {
    float s0 = v[0] + v[7], s1 = v[1] + v[6], s2 = v[2] + v[5], s3 = v[3] + v[4];
    float d0 = v[0] - v[7], d1 = v[1] - v[6], d2 = v[2] - v[5], d3 = v[3] - v[4];
    float e0 = s0 + s3, e1 = s1 + s2;
    float o0 = s0 - s3, o1 = s1 - s2;
    v[0] = K0 * (e0 + e1);
    v[4] = K0 * (e0 - e1);
    v[2] = K2 * o0 + K6 * o1;
    v[6] = K6 * o0 - K2 * o1;
    v[1] = K1 * d0 + K3 * d1 + K5 * d2 + K7 * d3;
    v[3] = K3 * d0 - K7 * d1 - K1 * d2 - K5 * d3;
    v[5] = K5 * d0 - K1 * d1 + K7 * d2 + K3 * d3;
    v[7] = K7 * d0 - K5 * d1 + K3 * d2 - K1 * d3;
}

// Streaming float4 load with L2 256B prefetch: batches the read stream at
// DRAM (adjacent warps' lines ride the prefetch window).
__device__ __forceinline__ float4 ldcs_pf256(const float4* p) {
    float4 v;
    asm volatile("ld.global.cs.L2::256B.v4.f32 {%0, %1, %2, %3}, [%4];"
                 : "=f"(v.x), "=f"(v.y), "=f"(v.z), "=f"(v.w)
                 : "l"(p));
    return v;
}

// Warp = 4 horizontally adjacent 8x8 blocks (an 8x32 tile, rows = 128B).
// Thread (j = lane>>2, b = lane&3): row j of block b. MLP_p1 = 2 (deliberate:
// deeper front-batching regressed via cross-CTA L1tex-queue contention).
// Transpose through padded per-warp SMEM (bank-conflict-free both directions).
__global__ void __launch_bounds__(256)
dct_quant_kernel(const float* __restrict__ x,
                 const float* __restrict__ q,
                 float* __restrict__ out,
                 int nwarps) {
    __shared__ float srq[8][64];         // per-warp 1/q -> no CTA-entry barrier
    __shared__ float tr[8][4][8][9];     // [warp][block][col][row], pad 9

    int wid  = threadIdx.x >> 5;
    int lane = threadIdx.x & 31;

    int w = blockIdx.x * 8 + wid;
    if (w >= nwarps) return;             // whole warps exit together
    int j = lane >> 2;   // row within block (becomes horizontal-freq index)
    int b = lane & 3;    // block within tile

    // tiles: 2048 planes x 16 block-rows x 4 tile-cols
    int img = w >> 6;
    int br  = (w >> 2) & 15;
    int tc  = w & 3;
    long tile = ((long)img << 14) + (br << 10) + (tc << 5);

    const float* base = x + tile + j * 128 + b * 8;

    // Streaming loads (use-once, evict-first) + L2 256B prefetch
    float4 lo = ldcs_pf256(reinterpret_cast<const float4*>(base));
    float4 hi = ldcs_pf256(reinterpret_cast<const float4*>(base + 4));

    // Per-warp q reciprocal init: independent of loads, covered by __syncwarp.
    srq[wid][lane]      = 1.0f / q[lane];
    srq[wid][lane + 32] = 1.0f / q[lane + 32];

    float r[8];
    r[0] = lo.x; r[1] = lo.y; r[2] = lo.z; r[3] = lo.w;
    r[4] = hi.x; r[5] = hi.y; r[6] = hi.z; r[7] = hi.w;

    // Row pass (along memory-contiguous dimension)
    dct8(r);

    // Transposed write: tr[wid][b][c][j] = r[c].
    // Banks (8b + 9c + j) mod 32: all 32 distinct for fixed c -> conflict-free.
    float* ts = &tr[wid][b][0][0];
    #pragma unroll
    for (int c = 0; c < 8; c++) ts[c * 9 + j] = r[c];

    __syncwarp();

    // Row-contiguous read of the transposed data: r[i] = R[i][j] (column j).
    // Banks (8b + 9j + i) mod 32: all 32 distinct for fixed i -> conflict-free.
    #pragma unroll
    for (int i = 0; i < 8; i++) r[i] = ts[j * 9 + i];

    // Column pass: register index v = vertical frequency, j = horizontal freq
    dct8(r);

    // Quantize + round-half-even + clip, store column-oriented (streaming).
    // For fixed v, warp writes tile + v*128 + {b*8+j over lanes}: one
    // contiguous, fully-coalesced 128B segment per STG.
    const float* sq = srq[wid];
    float* obase = out + tile + b * 8 + j;
    #pragma unroll
    for (int v = 0; v < 8; v++) {
        float y = rintf(r[v] * sq[v * 8 + j]);
        y = fminf(fmaxf(y, -128.0f), 127.0f);
        __stcs(obase + v * 128, y);
    }
}

extern "C" void kernel_launch(void* const* d_in, const int* in_sizes, int n_in,
                              void* d_out, int out_size) {
    const float* x = (const float*)d_in[0];
    const float* q = (const float*)d_in[1];
    float* out = (float*)d_out;

    int nelem  = in_sizes[0];         // 33554432
    int nwarps = nelem / 256;         // 131072 warps (4 blocks each)
    int grid   = (nwarps + 7) / 8;    // 16384 CTAs of 256 threads

    dct_quant_kernel<<<grid, 256>>>(x, q, out, nwarps);
}